// round 11
// baseline (speedup 1.0000x reference)
#include <cuda_runtime.h>
#include <cstdint>

#define EPC 8
// word offsets in dynamic smem
#define S_ABC 0        // 48
#define S_BC  64       // 16x16
#define S_WA  320      // float4[8][32] : WA[P][c]
#define S_W0T 1344     // W0 transposed [t][c] (256)
#define S_P1A 1600     // P1 buffer A: 8 warps x 580
#define S_P1B 6240     // P1 buffer B
#define P1WS  580
#define S_P2  10880    // 8 warps x 148
#define P2WS  148
#define S_B2H 12064    // [q2 8][132]
#define S_B2L 13120
#define S_Y2  14176    // [q2][f]
#define S_P3  14432
#define S_W3S 14688    // [q2][cq][f][4]
#define SMW   22880
#define SMEM_BYTES (SMW * 4)

__device__ __forceinline__ uint32_t pack_bf16x2(float lo, float hi) {
    uint32_t d;
    asm("cvt.rn.bf16x2.f32 %0, %1, %2;" : "=r"(d) : "f"(hi), "f"(lo));
    return d;
}
__device__ __forceinline__ float bf_lo(uint32_t v) { return __uint_as_float(v << 16); }
__device__ __forceinline__ float bf_hi(uint32_t v) { return __uint_as_float(v & 0xffff0000u); }
__device__ __forceinline__ void split2(float v0, float v1, uint32_t& h, uint32_t& l) {
    h = pack_bf16x2(v0, v1);
    l = pack_bf16x2(v0 - bf_lo(h), v1 - bf_hi(h));
}
__device__ __forceinline__ void mma_bf16(float& c0, float& c1, float& c2, float& c3,
                                         uint32_t a0, uint32_t a1, uint32_t a2, uint32_t a3,
                                         uint32_t b0, uint32_t b1) {
    asm("mma.sync.aligned.m16n8k16.row.col.f32.bf16.bf16.f32 "
        "{%0,%1,%2,%3},{%4,%5,%6,%7},{%8,%9},{%0,%1,%2,%3};"
        : "+f"(c0), "+f"(c1), "+f"(c2), "+f"(c3)
        : "r"(a0), "r"(a1), "r"(a2), "r"(a3), "r"(b0), "r"(b1));
}
__device__ __forceinline__ void ldm4(uint32_t& r0, uint32_t& r1, uint32_t& r2, uint32_t& r3,
                                     uint32_t saddr) {
    asm volatile("ldmatrix.sync.aligned.m8n8.x4.shared.b16 {%0,%1,%2,%3}, [%4];"
                 : "=r"(r0), "=r"(r1), "=r"(r2), "=r"(r3) : "r"(saddr));
}

__global__ __launch_bounds__(256, 2)
void ntc_fused(const int* __restrict__ gI, const int* __restrict__ gJ, const int* __restrict__ gK,
               const float* __restrict__ A, const float* __restrict__ Bm, const float* __restrict__ Cm,
               const float* __restrict__ W0, const float* __restrict__ b0,
               const float* __restrict__ W1, const float* __restrict__ b1,
               const float* __restrict__ W2, const float* __restrict__ b2,
               const float* __restrict__ W3, const float* __restrict__ b3,
               const float* __restrict__ FCW, const float* __restrict__ FCB,
               float* __restrict__ out, int n)
{
    extern __shared__ float sm[];
    uint32_t* smu = (uint32_t*)sm;
    const uint32_t smbase = (uint32_t)__cvta_generic_to_shared(sm);

    const int tid  = threadIdx.x;
    const int lane = tid & 31;
    const int wrp  = tid >> 5;
    const int tig  = lane & 3;
    const int gid  = lane >> 2;
    const int mt   = wrp & 1;
    const int kq   = wrp >> 1;

    // ---- A fragments for layer1 AND layer2 mma (bf16 hi/lo split) ----
    uint32_t a1h[16], a1l[16], a2h[16], a2l[16];
#pragma unroll
    for (int ch = 0; ch < 4; ++ch)
#pragma unroll
        for (int r = 0; r < 4; ++r) {
            const int fr = mt * 16 + gid + (r & 1) * 8;
            const int k  = kq * 64 + ch * 16 + (r >> 1) * 8 + 2 * tig;
            const float2 w1v = *(const float2*)&W1[fr * 256 + k];
            split2(w1v.x, w1v.y, a1h[ch * 4 + r], a1l[ch * 4 + r]);
            const float2 w2v = *(const float2*)&W2[fr * 256 + k];
            split2(w2v.x, w2v.y, a2h[ch * 4 + r], a2l[ch * 4 + r]);
        }

    // ---- W3 into persistent smem as [q2][cq][f][4] ----
#pragma unroll
    for (int r = 0; r < 32; ++r) {
        const int idx = tid + 256 * r;            // = f*256 + c*8 + q2
        const int f = idx >> 8, c = (idx >> 3) & 31, q2 = idx & 7;
        sm[S_W3S + ((q2 * 8 + (c >> 2)) * 32 + f) * 4 + (c & 3)] = W3[idx];
    }
    // ---- W0 transposed [t][c] into smem ----
    sm[S_W0T + (tid & 7) * 32 + (tid >> 3)] = W0[tid];

    // per-thread layer0 bias slice: channels kq*8 .. kq*8+7
    float b0r[8];
    {
        const float4 bq0 = *(const float4*)&b0[kq * 8];
        const float4 bq1 = *(const float4*)&b0[kq * 8 + 4];
        b0r[0]=bq0.x; b0r[1]=bq0.y; b0r[2]=bq0.z; b0r[3]=bq0.w;
        b0r[4]=bq1.x; b0r[5]=bq1.y; b0r[6]=bq1.z; b0r[7]=bq1.w;
    }
    const float bias1 = b1[lane], bias2 = b2[lane], bias3 = b3[lane];
    const float fcw = FCW[lane], fcb = FCB[0];

    // y1-reduce mapping
    const int rf   = tid & 31;
    const int rt1g = (tid >> 5) & 1;
    const int rq2i = tid >> 6;
    const int rmt = rf >> 4, r16 = rf & 15;
    const int rboff = rq2i * 144 + r16 * 8 + (r16 >> 2) * 4 + rt1g * 4;
    // y2-reduce mapping (tid<64)
    const int yc = tid & 31, yq2g = (tid >> 5) & 1;
    const int ymt = yc >> 4, yr16 = yc & 15;
    const int ybase = S_P2 + yr16 * 8 + (yr16 >> 2) * 4 + yq2g * 4;

    auto do_final = [&](int eo) {
        float s3 = sm[S_P3 + lane];
#pragma unroll
        for (int wi = 1; wi < 8; ++wi) s3 += sm[S_P3 + wi * 32 + lane];
        const float y3 = fmaxf(s3 + bias3, 0.f);
        float vv = fcw * y3;
#pragma unroll
        for (int off = 16; off; off >>= 1)
            vv += __shfl_xor_sync(0xffffffffu, vv, off);
        if (lane == 0)
            out[eo] = 1.0f / (1.0f + __expf(-(vv + fcb)));
    };

    // ---- fused layer0+layer1: B fragments computed in registers, mma, write P1 ----
    auto mma_pass = [&](int half, int p1base) {
        const int D1 = 2 * half + ((gid >> 2) & 1);
        const int P0 = 2 * D1 + (tig >> 1);
        const int qh = tig & 1;
        const int hb = (gid >> 1) & 1, wb = gid & 1;
#pragma unroll
        for (int nt = 0; nt < 4; ++nt) {
            const int H1 = 2 * (nt >> 1) + hb, Wd1 = 2 * (nt & 1) + wb;
            const float4 bcA = *(const float4*)&sm[S_BC + (4 * H1 + 2 * qh) * 16 + 4 * Wd1];
            const float4 bcB = *(const float4*)&sm[S_BC + (4 * H1 + 2 * qh + 1) * 16 + 4 * Wd1];
            float c0 = 0.f, c1 = 0.f, c2 = 0.f, c3 = 0.f;
#pragma unroll
            for (int ch = 0; ch < 4; ++ch) {
                const float4 wa0 = ((const float4*)(sm + S_WA))[P0 * 32 + kq * 8 + 2 * ch];
                const float4 wa1 = ((const float4*)(sm + S_WA))[P0 * 32 + kq * 8 + 2 * ch + 1];
                const float v00 = fmaxf(fmaf(wa0.x, bcA.x, fmaf(wa0.y, bcA.y, fmaf(wa0.z, bcB.x, fmaf(wa0.w, bcB.y, b0r[2*ch])))), 0.f);
                const float v01 = fmaxf(fmaf(wa0.x, bcA.z, fmaf(wa0.y, bcA.w, fmaf(wa0.z, bcB.z, fmaf(wa0.w, bcB.w, b0r[2*ch])))), 0.f);
                const float v10 = fmaxf(fmaf(wa1.x, bcA.x, fmaf(wa1.y, bcA.y, fmaf(wa1.z, bcB.x, fmaf(wa1.w, bcB.y, b0r[2*ch+1])))), 0.f);
                const float v11 = fmaxf(fmaf(wa1.x, bcA.z, fmaf(wa1.y, bcA.w, fmaf(wa1.z, bcB.z, fmaf(wa1.w, bcB.w, b0r[2*ch+1])))), 0.f);
                uint32_t bh0, bl0, bh1, bl1;
                split2(v00, v01, bh0, bl0);
                split2(v10, v11, bh1, bl1);
                mma_bf16(c0,c1,c2,c3, a1h[ch*4+0],a1h[ch*4+1],a1h[ch*4+2],a1h[ch*4+3], bh0, bh1);
                mma_bf16(c0,c1,c2,c3, a1h[ch*4+0],a1h[ch*4+1],a1h[ch*4+2],a1h[ch*4+3], bl0, bl1);
                mma_bf16(c0,c1,c2,c3, a1l[ch*4+0],a1l[ch*4+1],a1l[ch*4+2],a1l[ch*4+3], bh0, bh1);
            }
            float* p = sm + p1base + wrp * P1WS + nt * 144 + gid * 8 + (gid >> 2) * 4 + 2 * tig;
            *(float2*)p        = make_float2(c0, c1);
            *(float2*)(p + 72) = make_float2(c2, c3);
        }
    };

    auto reduce_half = [&](int half, int p1base) {
        float s0 = 0.f, s1 = 0.f, s2 = 0.f, s3 = 0.f;
#pragma unroll
        for (int kqi = 0; kqi < 4; ++kqi) {
            const float4 p = *(const float4*)&sm[p1base + (rmt + 2 * kqi) * P1WS + rboff];
            s0 += p.x; s1 += p.y; s2 += p.z; s3 += p.w;
        }
        const float y0  = fmaxf(s0 + bias1, 0.f);
        const float y1v = fmaxf(s1 + bias1, 0.f);
        const float y2v = fmaxf(s2 + bias1, 0.f);
        const float y3v = fmaxf(s3 + bias1, 0.f);
        uint32_t h0, l0, h1, l1;
        split2(y0, y1v, h0, l0);
        split2(y2v, y3v, h1, l1);
        const int q2 = half * 4 + rq2i;
        const int kp = rf * 4 + rt1g * 2;
        *(uint2*)&smu[S_B2H + q2 * 132 + kp] = make_uint2(h0, h1);
        *(uint2*)&smu[S_B2L + q2 * 132 + kp] = make_uint2(l0, l1);
    };

    const int ebase = blockIdx.x * EPC;
    int nel = n - ebase;
    if (nel <= 0) return;
    if (nel > EPC) nel = EPC;

    for (int e0 = 0; e0 < nel; ++e0) {
        const int e = ebase + e0;
        __syncthreads();   // prev P3 ready / smem reuse boundary

        if (wrp == 0) {
            if (e0 > 0) do_final(e - 1);
        } else if (tid >= 64 && tid < 112) {
            const int t = tid - 64;
            const int which = t >> 4, idx = t & 15;
            const int row = (which == 0) ? gI[e] : (which == 1 ? gJ[e] : gK[e]);
            const float* src = (which == 0) ? A : (which == 1 ? Bm : Cm);
            sm[S_ABC + t] = src[row * 16 + idx];
        }
        __syncthreads();

        // BC outer product + WA (w0 from smem, transposed: conflict-free)
        sm[S_BC + tid] = sm[S_ABC + 16 + (tid >> 4)] * sm[S_ABC + 32 + (tid & 15)];
        {
            const float a0 = sm[S_ABC + 2 * wrp], a1 = sm[S_ABC + 2 * wrp + 1];
            float w0v[8];
#pragma unroll
            for (int t = 0; t < 8; ++t) w0v[t] = sm[S_W0T + t * 32 + lane];
            ((float4*)(sm + S_WA))[wrp * 32 + lane] = make_float4(
                fmaf(w0v[0], a0, w0v[4] * a1),
                fmaf(w0v[1], a0, w0v[5] * a1),
                fmaf(w0v[2], a0, w0v[6] * a1),
                fmaf(w0v[3], a0, w0v[7] * a1));
        }
        __syncthreads();

        mma_pass(0, S_P1A);
        __syncthreads();

        // overlapped: mma pass (half1) into P1B + y1-reduce(half0) from P1A
        mma_pass(1, S_P1B);
        reduce_half(0, S_P1A);
        __syncthreads();

        reduce_half(1, S_P1B);
        __syncthreads();

        // layer2 mma (B2 via ldmatrix)
        {
            const uint32_t rowb = (uint32_t)((((lane & 7)) * 132 + kq * 32 + ((lane >> 3) << 2)) * 4);
            uint32_t h0,h1,h2,h3,h4,h5,h6,h7, l0,l1,l2,l3,l4,l5,l6,l7;
            ldm4(h0,h1,h2,h3, smbase + S_B2H*4 + rowb);
            ldm4(h4,h5,h6,h7, smbase + S_B2H*4 + rowb + 64);
            ldm4(l0,l1,l2,l3, smbase + S_B2L*4 + rowb);
            ldm4(l4,l5,l6,l7, smbase + S_B2L*4 + rowb + 64);
            float c0 = 0.f, c1 = 0.f, c2 = 0.f, c3 = 0.f;
            mma_bf16(c0,c1,c2,c3, a2h[0],a2h[1],a2h[2],a2h[3],     h0,h1);
            mma_bf16(c0,c1,c2,c3, a2h[0],a2h[1],a2h[2],a2h[3],     l0,l1);
            mma_bf16(c0,c1,c2,c3, a2l[0],a2l[1],a2l[2],a2l[3],     h0,h1);
            mma_bf16(c0,c1,c2,c3, a2h[4],a2h[5],a2h[6],a2h[7],     h2,h3);
            mma_bf16(c0,c1,c2,c3, a2h[4],a2h[5],a2h[6],a2h[7],     l2,l3);
            mma_bf16(c0,c1,c2,c3, a2l[4],a2l[5],a2l[6],a2l[7],     h2,h3);
            mma_bf16(c0,c1,c2,c3, a2h[8],a2h[9],a2h[10],a2h[11],   h4,h5);
            mma_bf16(c0,c1,c2,c3, a2h[8],a2h[9],a2h[10],a2h[11],   l4,l5);
            mma_bf16(c0,c1,c2,c3, a2l[8],a2l[9],a2l[10],a2l[11],   h4,h5);
            mma_bf16(c0,c1,c2,c3, a2h[12],a2h[13],a2h[14],a2h[15], h6,h7);
            mma_bf16(c0,c1,c2,c3, a2h[12],a2h[13],a2h[14],a2h[15], l6,l7);
            mma_bf16(c0,c1,c2,c3, a2l[12],a2l[13],a2l[14],a2l[15], h6,h7);
            float* p = sm + S_P2 + wrp * P2WS + gid * 8 + (gid >> 2) * 4 + 2 * tig;
            *(float2*)p        = make_float2(c0, c1);
            *(float2*)(p + 72) = make_float2(c2, c3);
        }
        __syncthreads();

        // y2 reduce -> Y2[q2][f]
        if (tid < 64) {
            float s0 = 0.f, s1 = 0.f, s2 = 0.f, s3 = 0.f;
#pragma unroll
            for (int kqi = 0; kqi < 4; ++kqi) {
                const float4 p = *(const float4*)&sm[ybase + (ymt + 2 * kqi) * P2WS];
                s0 += p.x; s1 += p.y; s2 += p.z; s3 += p.w;
            }
            sm[S_Y2 + (4 * yq2g + 0) * 32 + yc] = fmaxf(s0 + bias2, 0.f);
            sm[S_Y2 + (4 * yq2g + 1) * 32 + yc] = fmaxf(s1 + bias2, 0.f);
            sm[S_Y2 + (4 * yq2g + 2) * 32 + yc] = fmaxf(s2 + bias2, 0.f);
            sm[S_Y2 + (4 * yq2g + 3) * 32 + yc] = fmaxf(s3 + bias2, 0.f);
        }
        __syncthreads();

        // layer3 partial: warp = 4-channel slice, lane = f
        {
            float acc = 0.f;
#pragma unroll
            for (int q2 = 0; q2 < 8; ++q2) {
                const float4 y2v = *(const float4*)&sm[S_Y2 + q2 * 32 + 4 * wrp];
                const float4 w3v = *(const float4*)&sm[S_W3S + ((q2 * 8 + wrp) * 32 + lane) * 4];
                acc = fmaf(w3v.x, y2v.x, acc);
                acc = fmaf(w3v.y, y2v.y, acc);
                acc = fmaf(w3v.z, y2v.z, acc);
                acc = fmaf(w3v.w, y2v.w, acc);
            }
            sm[S_P3 + wrp * 32 + lane] = acc;
        }
        // next iteration's top barrier covers P3
    }

    __syncthreads();
    if (wrp == 0) do_final(ebase + nel - 1);
}

extern "C" void kernel_launch(void* const* d_in, const int* in_sizes, int n_in,
                              void* d_out, int out_size) {
    const int*   gI  = (const int*)d_in[0];
    const int*   gJ  = (const int*)d_in[1];
    const int*   gK  = (const int*)d_in[2];
    const float* A   = (const float*)d_in[3];
    const float* B   = (const float*)d_in[4];
    const float* C   = (const float*)d_in[5];
    const float* W0  = (const float*)d_in[6];
    const float* b0  = (const float*)d_in[7];
    const float* W1  = (const float*)d_in[8];
    const float* b1  = (const float*)d_in[9];
    const float* W2  = (const float*)d_in[10];
    const float* b2  = (const float*)d_in[11];
    const float* W3  = (const float*)d_in[12];
    const float* b3  = (const float*)d_in[13];
    const float* FCW = (const float*)d_in[14];
    const float* FCB = (const float*)d_in[15];

    cudaFuncSetAttribute(ntc_fused, cudaFuncAttributeMaxDynamicSharedMemorySize, SMEM_BYTES);

    const int n = in_sizes[0];
    const int grid = (n + EPC - 1) / EPC;
    ntc_fused<<<grid, 256, SMEM_BYTES>>>(gI, gJ, gK, A, B, C, W0, b0, W1, b1, W2, b2,
                                         W3, b3, FCW, FCB, (float*)d_out, n);
}

// round 14
// speedup vs baseline: 1.4420x; 1.4420x over previous
#include <cuda_runtime.h>
#include <cuda_fp16.h>
#include <cstdint>

#define EPC 8
// word offsets in dynamic smem
#define S_B1  0        // [32 rows][132] fp16x2 (single-term B, layer1)
#define S_ABC 4224     // 48
#define S_BC  4288     // 16x16
#define S_WA  4544     // float4[8][32]
#define S_P1  5568     // 8 warps x 580 (row stride 8 + pad4/4rows, nt stride 144)
#define P1WS  580
#define S_P2  10208    // 8 warps x 148
#define P2WS  148
#define S_B2  11392    // [q2 8][132] fp16x2
#define S_Y2  12448    // [q2][f]
#define S_P3  12704
#define S_W3S 12960    // [q2][cq][f][4]
#define SMW   21152
#define SMEM_BYTES (SMW * 4)

__device__ __forceinline__ uint32_t pack_f16x2(float lo, float hi) {
    uint32_t d;
    asm("cvt.rn.f16x2.f32 %0, %1, %2;" : "=r"(d) : "f"(hi), "f"(lo));
    return d;
}
// fp16 hi/lo split for weights (A operands)
__device__ __forceinline__ void split2h(float v0, float v1, uint32_t& h, uint32_t& l) {
    h = pack_f16x2(v0, v1);
    __half2 hh;
    *(uint32_t*)&hh = h;
    l = pack_f16x2(v0 - __low2float(hh), v1 - __high2float(hh));
}
__device__ __forceinline__ void mma_f16(float& c0, float& c1, float& c2, float& c3,
                                        uint32_t a0, uint32_t a1, uint32_t a2, uint32_t a3,
                                        uint32_t b0, uint32_t b1) {
    asm("mma.sync.aligned.m16n8k16.row.col.f32.f16.f16.f32 "
        "{%0,%1,%2,%3},{%4,%5,%6,%7},{%8,%9},{%0,%1,%2,%3};"
        : "+f"(c0), "+f"(c1), "+f"(c2), "+f"(c3)
        : "r"(a0), "r"(a1), "r"(a2), "r"(a3), "r"(b0), "r"(b1));
}
__device__ __forceinline__ void ldm4(uint32_t& r0, uint32_t& r1, uint32_t& r2, uint32_t& r3,
                                     uint32_t saddr) {
    asm volatile("ldmatrix.sync.aligned.m8n8.x4.shared.b16 {%0,%1,%2,%3}, [%4];"
                 : "=r"(r0), "=r"(r1), "=r"(r2), "=r"(r3) : "r"(saddr));
}

__global__ __launch_bounds__(256, 2)
void ntc_fused(const int* __restrict__ gI, const int* __restrict__ gJ, const int* __restrict__ gK,
               const float* __restrict__ A, const float* __restrict__ Bm, const float* __restrict__ Cm,
               const float* __restrict__ W0, const float* __restrict__ b0,
               const float* __restrict__ W1, const float* __restrict__ b1,
               const float* __restrict__ W2, const float* __restrict__ b2,
               const float* __restrict__ W3, const float* __restrict__ b3,
               const float* __restrict__ FCW, const float* __restrict__ FCB,
               float* __restrict__ out, int n)
{
    extern __shared__ float sm[];
    uint32_t* smu = (uint32_t*)sm;
    const uint32_t smbase = (uint32_t)__cvta_generic_to_shared(sm);

    const int tid  = threadIdx.x;
    const int lane = tid & 31;
    const int wrp  = tid >> 5;
    const int tig  = lane & 3;
    const int gid  = lane >> 2;
    const int mt   = wrp & 1;
    const int kq   = wrp >> 1;

    // ---- A fragments for layer1/layer2 (fp16 hi/lo split of W1, W2) ----
    uint32_t a1h[16], a1l[16], a2h[16], a2l[16];
#pragma unroll
    for (int ch = 0; ch < 4; ++ch)
#pragma unroll
        for (int r = 0; r < 4; ++r) {
            const int fr = mt * 16 + gid + (r & 1) * 8;
            const int k  = kq * 64 + ch * 16 + (r >> 1) * 8 + 2 * tig;
            const float2 w1v = *(const float2*)&W1[fr * 256 + k];
            split2h(w1v.x, w1v.y, a1h[ch * 4 + r], a1l[ch * 4 + r]);
            const float2 w2v = *(const float2*)&W2[fr * 256 + k];
            split2h(w2v.x, w2v.y, a2h[ch * 4 + r], a2l[ch * 4 + r]);
        }

    // ---- W3 into persistent smem as [q2][cq][f][4] ----
#pragma unroll
    for (int r = 0; r < 32; ++r) {
        const int idx = tid + 256 * r;            // = f*256 + c*8 + q2
        const int f = idx >> 8, c = (idx >> 3) & 31, q2 = idx & 7;
        sm[S_W3S + ((q2 * 8 + (c >> 2)) * 32 + f) * 4 + (c & 3)] = W3[idx];
    }

    float w0r[8];
#pragma unroll
    for (int t = 0; t < 8; ++t) w0r[t] = W0[lane * 8 + t];
    const float bias0 = b0[lane], bias1 = b1[lane], bias2 = b2[lane], bias3 = b3[lane];
    const float fcw = FCW[lane], fcb = FCB[0];

    const int wd = (wrp >> 2) & 1, wh = (wrp >> 1) & 1, ww = wrp & 1;
    // y1-reduce mapping
    const int rf   = tid & 31;
    const int rt1g = (tid >> 5) & 1;
    const int rq2i = tid >> 6;
    const int rmt = rf >> 4, r16 = rf & 15;
    const int rbase = S_P1 + rq2i * 144 + r16 * 8 + (r16 >> 2) * 4 + rt1g * 4;
    // y2-reduce mapping (tid<64)
    const int yc = tid & 31, yq2g = (tid >> 5) & 1;
    const int ymt = yc >> 4, yr16 = yc & 15;
    const int ybase = S_P2 + yr16 * 8 + (yr16 >> 2) * 4 + yq2g * 4;

    auto do_final = [&](int eo) {
        float s3 = sm[S_P3 + lane];
#pragma unroll
        for (int wi = 1; wi < 8; ++wi) s3 += sm[S_P3 + wi * 32 + lane];
        const float y3 = fmaxf(s3 + bias3, 0.f);
        float vv = fcw * y3;
#pragma unroll
        for (int off = 16; off; off >>= 1)
            vv += __shfl_xor_sync(0xffffffffu, vv, off);
        if (lane == 0)
            out[eo] = 1.0f / (1.0f + __expf(-(vv + fcb)));
    };

    // ---- layer0 for one d2-half: B1 rows as fp16x2 ----
    auto layer0 = [&](int half) {
        const int D1 = 2 * half + wd;
        const float4 wa0 = ((const float4*)(sm + S_WA))[(2 * D1) * 32 + lane];
        const float4 wa1 = ((const float4*)(sm + S_WA))[(2 * D1 + 1) * 32 + lane];
#pragma unroll
        for (int q2i = 0; q2i < 4; ++q2i) {
            const int H1 = 2 * (q2i >> 1) + wh, Wd1 = 2 * (q2i & 1) + ww;
            float v[8];
#pragma unroll
            for (int qh = 0; qh < 2; ++qh) {
                const float4 bcA = *(const float4*)&sm[S_BC + (4 * H1 + 2 * qh) * 16 + 4 * Wd1];
                const float4 bcB = *(const float4*)&sm[S_BC + (4 * H1 + 2 * qh + 1) * 16 + 4 * Wd1];
                v[qh*2+0]   = fmaxf(fmaf(wa0.x, bcA.x, fmaf(wa0.y, bcA.y, fmaf(wa0.z, bcB.x, fmaf(wa0.w, bcB.y, bias0)))), 0.f);
                v[qh*2+1]   = fmaxf(fmaf(wa0.x, bcA.z, fmaf(wa0.y, bcA.w, fmaf(wa0.z, bcB.z, fmaf(wa0.w, bcB.w, bias0)))), 0.f);
                v[4+qh*2+0] = fmaxf(fmaf(wa1.x, bcA.x, fmaf(wa1.y, bcA.y, fmaf(wa1.z, bcB.x, fmaf(wa1.w, bcB.y, bias0)))), 0.f);
                v[4+qh*2+1] = fmaxf(fmaf(wa1.x, bcA.z, fmaf(wa1.y, bcA.w, fmaf(wa1.z, bcB.z, fmaf(wa1.w, bcB.w, bias0)))), 0.f);
            }
            const int rowoff = (q2i * 8 + wrp) * 132 + 4 * lane;
            *(uint4*)&smu[S_B1 + rowoff] = make_uint4(
                pack_f16x2(v[0], v[1]), pack_f16x2(v[2], v[3]),
                pack_f16x2(v[4], v[5]), pack_f16x2(v[6], v[7]));
        }
    };

    // ---- layer1 mma pass: reads B1, writes P1 ----
    auto mma1 = [&]() {
#pragma unroll
        for (int nt = 0; nt < 4; ++nt) {
            const uint32_t rowb = (uint32_t)(((nt * 8 + (lane & 7)) * 132 + kq * 32 + ((lane >> 3) << 2)) * 4);
            uint32_t bb0,bb1,bb2,bb3,bb4,bb5,bb6,bb7;
            ldm4(bb0,bb1,bb2,bb3, smbase + S_B1*4 + rowb);
            ldm4(bb4,bb5,bb6,bb7, smbase + S_B1*4 + rowb + 64);
            float c0 = 0.f, c1 = 0.f, c2 = 0.f, c3 = 0.f;
            mma_f16(c0,c1,c2,c3, a1h[0],a1h[1],a1h[2],a1h[3],     bb0,bb1);
            mma_f16(c0,c1,c2,c3, a1l[0],a1l[1],a1l[2],a1l[3],     bb0,bb1);
            mma_f16(c0,c1,c2,c3, a1h[4],a1h[5],a1h[6],a1h[7],     bb2,bb3);
            mma_f16(c0,c1,c2,c3, a1l[4],a1l[5],a1l[6],a1l[7],     bb2,bb3);
            mma_f16(c0,c1,c2,c3, a1h[8],a1h[9],a1h[10],a1h[11],   bb4,bb5);
            mma_f16(c0,c1,c2,c3, a1l[8],a1l[9],a1l[10],a1l[11],   bb4,bb5);
            mma_f16(c0,c1,c2,c3, a1h[12],a1h[13],a1h[14],a1h[15], bb6,bb7);
            mma_f16(c0,c1,c2,c3, a1l[12],a1l[13],a1l[14],a1l[15], bb6,bb7);
            float* p = sm + S_P1 + wrp * P1WS + nt * 144 + gid * 8 + (gid >> 2) * 4 + 2 * tig;
            *(float2*)p        = make_float2(c0, c1);
            *(float2*)(p + 72) = make_float2(c2, c3);
        }
    };

    auto reduce_sum = [&](float& s0, float& s1, float& s2, float& s3) {
        s0 = s1 = s2 = s3 = 0.f;
#pragma unroll
        for (int kqi = 0; kqi < 4; ++kqi) {
            const float4 p = *(const float4*)&sm[rbase + (rmt + 2 * kqi) * P1WS];
            s0 += p.x; s1 += p.y; s2 += p.z; s3 += p.w;
        }
    };
    auto reduce_emit = [&](int half, float s0, float s1, float s2, float s3) {
        const float y0  = fmaxf(s0 + bias1, 0.f);
        const float y1v = fmaxf(s1 + bias1, 0.f);
        const float y2v = fmaxf(s2 + bias1, 0.f);
        const float y3v = fmaxf(s3 + bias1, 0.f);
        const int q2 = half * 4 + rq2i;
        const int kp = rf * 4 + rt1g * 2;
        *(uint2*)&smu[S_B2 + q2 * 132 + kp] =
            make_uint2(pack_f16x2(y0, y1v), pack_f16x2(y2v, y3v));
    };

    const int ebase = blockIdx.x * EPC;
    int nel = n - ebase;
    if (nel <= 0) return;
    if (nel > EPC) nel = EPC;

    for (int e0 = 0; e0 < nel; ++e0) {
        const int e = ebase + e0;
        __syncthreads();   // prev P3 ready / smem reuse boundary

        if (wrp == 0) {
            if (e0 > 0) do_final(e - 1);
        } else if (tid >= 64 && tid < 112) {
            const int t = tid - 64;
            const int which = t >> 4, idx = t & 15;
            const int row = (which == 0) ? gI[e] : (which == 1 ? gJ[e] : gK[e]);
            const float* src = (which == 0) ? A : (which == 1 ? Bm : Cm);
            sm[S_ABC + t] = src[row * 16 + idx];
        }
        __syncthreads();

        // BC outer product + WA
        sm[S_BC + tid] = sm[S_ABC + 16 + (tid >> 4)] * sm[S_ABC + 32 + (tid & 15)];
        {
            const float a0 = sm[S_ABC + 2 * wrp], a1 = sm[S_ABC + 2 * wrp + 1];
            ((float4*)(sm + S_WA))[wrp * 32 + lane] = make_float4(
                fmaf(w0r[0], a0, w0r[4] * a1),
                fmaf(w0r[1], a0, w0r[5] * a1),
                fmaf(w0r[2], a0, w0r[6] * a1),
                fmaf(w0r[3], a0, w0r[7] * a1));
        }
        __syncthreads();

        layer0(0);
        __syncthreads();

        mma1();
        __syncthreads();

        // merged: y1-reduce(half0) + layer0(half1)
        {
            float s0, s1, s2, s3;
            reduce_sum(s0, s1, s2, s3);
            layer0(1);
            reduce_emit(0, s0, s1, s2, s3);
        }
        __syncthreads();

        mma1();
        __syncthreads();

        {
            float s0, s1, s2, s3;
            reduce_sum(s0, s1, s2, s3);
            reduce_emit(1, s0, s1, s2, s3);
        }
        __syncthreads();

        // layer2 mma
        {
            const uint32_t rowb = (uint32_t)((((lane & 7)) * 132 + kq * 32 + ((lane >> 3) << 2)) * 4);
            uint32_t bb0,bb1,bb2,bb3,bb4,bb5,bb6,bb7;
            ldm4(bb0,bb1,bb2,bb3, smbase + S_B2*4 + rowb);
            ldm4(bb4,bb5,bb6,bb7, smbase + S_B2*4 + rowb + 64);
            float c0 = 0.f, c1 = 0.f, c2 = 0.f, c3 = 0.f;
            mma_f16(c0,c1,c2,c3, a2h[0],a2h[1],a2h[2],a2h[3],     bb0,bb1);
            mma_f16(c0,c1,c2,c3, a2l[0],a2l[1],a2l[2],a2l[3],     bb0,bb1);
            mma_f16(c0,c1,c2,c3, a2h[4],a2h[5],a2h[6],a2h[7],     bb2,bb3);
            mma_f16(c0,c1,c2,c3, a2l[4],a2l[5],a2l[6],a2l[7],     bb2,bb3);
            mma_f16(c0,c1,c2,c3, a2h[8],a2h[9],a2h[10],a2h[11],   bb4,bb5);
            mma_f16(c0,c1,c2,c3, a2l[8],a2l[9],a2l[10],a2l[11],   bb4,bb5);
            mma_f16(c0,c1,c2,c3, a2h[12],a2h[13],a2h[14],a2h[15], bb6,bb7);
            mma_f16(c0,c1,c2,c3, a2l[12],a2l[13],a2l[14],a2l[15], bb6,bb7);
            float* p = sm + S_P2 + wrp * P2WS + gid * 8 + (gid >> 2) * 4 + 2 * tig;
            *(float2*)p        = make_float2(c0, c1);
            *(float2*)(p + 72) = make_float2(c2, c3);
        }
        __syncthreads();

        // y2 reduce -> Y2[q2][f]
        if (tid < 64) {
            float s0 = 0.f, s1 = 0.f, s2 = 0.f, s3 = 0.f;
#pragma unroll
            for (int kqi = 0; kqi < 4; ++kqi) {
                const float4 p = *(const float4*)&sm[ybase + (ymt + 2 * kqi) * P2WS];
                s0 += p.x; s1 += p.y; s2 += p.z; s3 += p.w;
            }
            sm[S_Y2 + (4 * yq2g + 0) * 32 + yc] = fmaxf(s0 + bias2, 0.f);
            sm[S_Y2 + (4 * yq2g + 1) * 32 + yc] = fmaxf(s1 + bias2, 0.f);
            sm[S_Y2 + (4 * yq2g + 2) * 32 + yc] = fmaxf(s2 + bias2, 0.f);
            sm[S_Y2 + (4 * yq2g + 3) * 32 + yc] = fmaxf(s3 + bias2, 0.f);
        }
        __syncthreads();

        // layer3 partial: warp = 4-channel slice, lane = f
        {
            float acc = 0.f;
#pragma unroll
            for (int q2 = 0; q2 < 8; ++q2) {
                const float4 y2v = *(const float4*)&sm[S_Y2 + q2 * 32 + 4 * wrp];
                const float4 w3v = *(const float4*)&sm[S_W3S + ((q2 * 8 + wrp) * 32 + lane) * 4];
                acc = fmaf(w3v.x, y2v.x, acc);
                acc = fmaf(w3v.y, y2v.y, acc);
                acc = fmaf(w3v.z, y2v.z, acc);
                acc = fmaf(w3v.w, y2v.w, acc);
            }
            sm[S_P3 + wrp * 32 + lane] = acc;
        }
        // next iteration's top barrier covers P3
    }

    __syncthreads();
    if (wrp == 0) do_final(ebase + nel - 1);
}

extern "C" void kernel_launch(void* const* d_in, const int* in_sizes, int n_in,
                              void* d_out, int out_size) {
    const int*   gI  = (const int*)d_in[0];
    const int*   gJ  = (const int*)d_in[1];
    const int*   gK  = (const int*)d_in[2];
    const float* A   = (const float*)d_in[3];
    const float* B   = (const float*)d_in[4];
    const float* C   = (const float*)d_in[5];
    const float* W0  = (const float*)d_in[6];
    const float* b0  = (const float*)d_in[7];
    const float* W1  = (const float*)d_in[8];
    const float* b1  = (const float*)d_in[9];
    const float* W2  = (const float*)d_in[10];
    const float* b2  = (const float*)d_in[11];
    const float* W3  = (const float*)d_in[12];
    const float* b3  = (const float*)d_in[13];
    const float* FCW = (const float*)d_in[14];
    const float* FCB = (const float*)d_in[15];

    cudaFuncSetAttribute(ntc_fused, cudaFuncAttributeMaxDynamicSharedMemorySize, SMEM_BYTES);

    const int n = in_sizes[0];
    const int grid = (n + EPC - 1) / EPC;
    ntc_fused<<<grid, 256, SMEM_BYTES>>>(gI, gJ, gK, A, B, C, W0, b0, W1, b1, W2, b2,
                                         W3, b3, FCW, FCB, (float*)d_out, n);
}

// round 15
// speedup vs baseline: 1.6784x; 1.1640x over previous
#include <cuda_runtime.h>
#include <cuda_fp16.h>
#include <cstdint>

#define EPC 8
// word offsets in dynamic smem
#define S_B1  0        // [32 rows][132] fp16x2 (layer1 B, one half at a time)
#define S_ABC 4224     // 48
#define S_BC  4288     // 16x16
#define S_WA  4544     // float4[8][32]
#define S_P1  5568     // 8 rows x 580 (row = 2*kq+mt)
#define P1WS  580
#define S_P2  10208    // 16 rows x 148 (row = 2*oct+mt)
#define P2WS  148
#define S_B2  12576    // [q2 8][132] fp16x2
#define S_Y2  13632    // [q2][f]
#define S_P3  13888
#define S_W3S 14144    // packed fp16: uint2[(q2*8+cq)*32+f] = 4 channel-halves
#define SMW   18240
#define SMEM_BYTES (SMW * 4)

__device__ __forceinline__ uint32_t pack_f16x2(float lo, float hi) {
    uint32_t d;
    asm("cvt.rn.f16x2.f32 %0, %1, %2;" : "=r"(d) : "f"(hi), "f"(lo));
    return d;
}
__device__ __forceinline__ void mma_f16(float& c0, float& c1, float& c2, float& c3,
                                        uint32_t a0, uint32_t a1, uint32_t a2, uint32_t a3,
                                        uint32_t b0, uint32_t b1) {
    asm("mma.sync.aligned.m16n8k16.row.col.f32.f16.f16.f32 "
        "{%0,%1,%2,%3},{%4,%5,%6,%7},{%8,%9},{%0,%1,%2,%3};"
        : "+f"(c0), "+f"(c1), "+f"(c2), "+f"(c3)
        : "r"(a0), "r"(a1), "r"(a2), "r"(a3), "r"(b0), "r"(b1));
}
__device__ __forceinline__ void ldm4(uint32_t& r0, uint32_t& r1, uint32_t& r2, uint32_t& r3,
                                     uint32_t saddr) {
    asm volatile("ldmatrix.sync.aligned.m8n8.x4.shared.b16 {%0,%1,%2,%3}, [%4];"
                 : "=r"(r0), "=r"(r1), "=r"(r2), "=r"(r3) : "r"(saddr));
}

__global__ __launch_bounds__(256, 2)
void ntc_fused(const int* __restrict__ gI, const int* __restrict__ gJ, const int* __restrict__ gK,
               const float* __restrict__ A, const float* __restrict__ Bm, const float* __restrict__ Cm,
               const float* __restrict__ W0, const float* __restrict__ b0,
               const float* __restrict__ W1, const float* __restrict__ b1,
               const float* __restrict__ W2, const float* __restrict__ b2,
               const float* __restrict__ W3, const float* __restrict__ b3,
               const float* __restrict__ FCW, const float* __restrict__ FCB,
               float* __restrict__ out, int n)
{
    extern __shared__ float sm[];
    uint32_t* smu = (uint32_t*)sm;
    const uint32_t smbase = (uint32_t)__cvta_generic_to_shared(sm);

    const int tid  = threadIdx.x;
    const int lane = tid & 31;
    const int wrp  = tid >> 5;
    const int tig  = lane & 3;
    const int gid  = lane >> 2;
    const int ntg  = wrp & 1;     // layer1: nt-group {0,1} -> nts {0,1}/{2,3}
    const int kq   = wrp >> 1;    // layer1: K-quarter (64 of 256)
    // layer2: warp = K-octant (wrp*32)

    // ---- A fragments, single-term fp16, BOTH m-tiles per warp ----
    uint32_t a1[32];   // layer1: [mt][ch*4+r]
#pragma unroll
    for (int mt2 = 0; mt2 < 2; ++mt2)
#pragma unroll
        for (int ch = 0; ch < 4; ++ch)
#pragma unroll
            for (int r = 0; r < 4; ++r) {
                const int fr = mt2 * 16 + gid + (r & 1) * 8;
                const int k  = kq * 64 + ch * 16 + (r >> 1) * 8 + 2 * tig;
                const float2 w = *(const float2*)&W1[fr * 256 + k];
                a1[mt2 * 16 + ch * 4 + r] = pack_f16x2(w.x, w.y);
            }
    uint32_t a2[16];   // layer2: [mt][kc*4+r], K-octant = wrp
#pragma unroll
    for (int mt2 = 0; mt2 < 2; ++mt2)
#pragma unroll
        for (int kc = 0; kc < 2; ++kc)
#pragma unroll
            for (int r = 0; r < 4; ++r) {
                const int fr = mt2 * 16 + gid + (r & 1) * 8;
                const int k  = wrp * 32 + kc * 16 + (r >> 1) * 8 + 2 * tig;
                const float2 w = *(const float2*)&W2[fr * 256 + k];
                a2[mt2 * 8 + kc * 4 + r] = pack_f16x2(w.x, w.y);
            }

    // ---- W3 packed fp16 quads: uint2[(q2*8+cq)*32+f] = channels 4cq..4cq+3 ----
#pragma unroll
    for (int r = 0; r < 16; ++r) {
        const int idx = tid + 256 * r;    // pair index: f | cp | q2
        const int f = idx >> 7, rem = idx & 127, cp = rem >> 3, q2 = rem & 7;
        const float w3a = W3[f * 256 + (2 * cp) * 8 + q2];
        const float w3b = W3[f * 256 + (2 * cp + 1) * 8 + q2];
        smu[S_W3S + ((q2 * 8 + (cp >> 1)) * 32 + f) * 2 + (cp & 1)] = pack_f16x2(w3a, w3b);
    }

    float w0r[8];
#pragma unroll
    for (int t = 0; t < 8; ++t) w0r[t] = W0[lane * 8 + t];
    const float bias0 = b0[lane], bias1 = b1[lane], bias2 = b2[lane], bias3 = b3[lane];
    const float fcw = FCW[lane], fcb = FCB[0];

    const int wd = (wrp >> 2) & 1, wh = (wrp >> 1) & 1, ww = wrp & 1;
    // y1-reduce mapping (P1 rows = 2*kq + mt, unchanged)
    const int rf   = tid & 31;
    const int rt1g = (tid >> 5) & 1;
    const int rq2i = tid >> 6;
    const int rmt = rf >> 4, r16 = rf & 15;
    const int rbase = S_P1 + rq2i * 144 + r16 * 8 + (r16 >> 2) * 4 + rt1g * 4;
    // y2-reduce mapping (tid<64); P2 rows = 2*oct + mt
    const int yc = tid & 31, yq2g = (tid >> 5) & 1;
    const int ymt = yc >> 4, yr16 = yc & 15;
    const int ybase = S_P2 + yr16 * 8 + (yr16 >> 2) * 4 + yq2g * 4;

    auto do_final = [&](int eo) {
        float s3 = sm[S_P3 + lane];
#pragma unroll
        for (int wi = 1; wi < 8; ++wi) s3 += sm[S_P3 + wi * 32 + lane];
        const float y3 = fmaxf(s3 + bias3, 0.f);
        float vv = fcw * y3;
#pragma unroll
        for (int off = 16; off; off >>= 1)
            vv += __shfl_xor_sync(0xffffffffu, vv, off);
        if (lane == 0)
            out[eo] = 1.0f / (1.0f + __expf(-(vv + fcb)));
    };

    // ---- layer0 for one d2-half: B1 rows as fp16x2 ----
    auto layer0 = [&](int half) {
        const int D1 = 2 * half + wd;
        const float4 wa0 = ((const float4*)(sm + S_WA))[(2 * D1) * 32 + lane];
        const float4 wa1 = ((const float4*)(sm + S_WA))[(2 * D1 + 1) * 32 + lane];
#pragma unroll
        for (int q2i = 0; q2i < 4; ++q2i) {
            const int H1 = 2 * (q2i >> 1) + wh, Wd1 = 2 * (q2i & 1) + ww;
            float v[8];
#pragma unroll
            for (int qh = 0; qh < 2; ++qh) {
                const float4 bcA = *(const float4*)&sm[S_BC + (4 * H1 + 2 * qh) * 16 + 4 * Wd1];
                const float4 bcB = *(const float4*)&sm[S_BC + (4 * H1 + 2 * qh + 1) * 16 + 4 * Wd1];
                v[qh*2+0]   = fmaxf(fmaf(wa0.x, bcA.x, fmaf(wa0.y, bcA.y, fmaf(wa0.z, bcB.x, fmaf(wa0.w, bcB.y, bias0)))), 0.f);
                v[qh*2+1]   = fmaxf(fmaf(wa0.x, bcA.z, fmaf(wa0.y, bcA.w, fmaf(wa0.z, bcB.z, fmaf(wa0.w, bcB.w, bias0)))), 0.f);
                v[4+qh*2+0] = fmaxf(fmaf(wa1.x, bcA.x, fmaf(wa1.y, bcA.y, fmaf(wa1.z, bcB.x, fmaf(wa1.w, bcB.y, bias0)))), 0.f);
                v[4+qh*2+1] = fmaxf(fmaf(wa1.x, bcA.z, fmaf(wa1.y, bcA.w, fmaf(wa1.z, bcB.z, fmaf(wa1.w, bcB.w, bias0)))), 0.f);
            }
            const int rowoff = (q2i * 8 + wrp) * 132 + 4 * lane;
            *(uint4*)&smu[S_B1 + rowoff] = make_uint4(
                pack_f16x2(v[0], v[1]), pack_f16x2(v[2], v[3]),
                pack_f16x2(v[4], v[5]), pack_f16x2(v[6], v[7]));
        }
    };

    // ---- layer1 mma: warp = (kq, ntg), both m-tiles; reads B1, writes P1 ----
    auto mma1 = [&]() {
#pragma unroll
        for (int nti = 0; nti < 2; ++nti) {
            const int nt = 2 * ntg + nti;
            const uint32_t rowb = (uint32_t)(((nt * 8 + (lane & 7)) * 132 + kq * 32 + ((lane >> 3) << 2)) * 4);
            uint32_t bb0,bb1,bb2,bb3,bb4,bb5,bb6,bb7;
            ldm4(bb0,bb1,bb2,bb3, smbase + S_B1*4 + rowb);
            ldm4(bb4,bb5,bb6,bb7, smbase + S_B1*4 + rowb + 64);
#pragma unroll
            for (int mt2 = 0; mt2 < 2; ++mt2) {
                const uint32_t* a = a1 + mt2 * 16;
                float c0 = 0.f, c1 = 0.f, c2 = 0.f, c3 = 0.f;
                mma_f16(c0,c1,c2,c3, a[0],a[1],a[2],a[3],     bb0,bb1);
                mma_f16(c0,c1,c2,c3, a[4],a[5],a[6],a[7],     bb2,bb3);
                mma_f16(c0,c1,c2,c3, a[8],a[9],a[10],a[11],   bb4,bb5);
                mma_f16(c0,c1,c2,c3, a[12],a[13],a[14],a[15], bb6,bb7);
                float* p = sm + S_P1 + (2 * kq + mt2) * P1WS + nt * 144 + gid * 8 + (gid >> 2) * 4 + 2 * tig;
                *(float2*)p        = make_float2(c0, c1);
                *(float2*)(p + 72) = make_float2(c2, c3);
            }
        }
    };

    auto reduce_sum = [&](float& s0, float& s1, float& s2, float& s3) {
        s0 = s1 = s2 = s3 = 0.f;
#pragma unroll
        for (int kqi = 0; kqi < 4; ++kqi) {
            const float4 p = *(const float4*)&sm[rbase + (rmt + 2 * kqi) * P1WS];
            s0 += p.x; s1 += p.y; s2 += p.z; s3 += p.w;
        }
    };
    auto reduce_emit = [&](int half, float s0, float s1, float s2, float s3) {
        const float y0  = fmaxf(s0 + bias1, 0.f);
        const float y1v = fmaxf(s1 + bias1, 0.f);
        const float y2v = fmaxf(s2 + bias1, 0.f);
        const float y3v = fmaxf(s3 + bias1, 0.f);
        const int q2 = half * 4 + rq2i;
        const int kp = rf * 4 + rt1g * 2;
        *(uint2*)&smu[S_B2 + q2 * 132 + kp] =
            make_uint2(pack_f16x2(y0, y1v), pack_f16x2(y2v, y3v));
    };

    const int ebase = blockIdx.x * EPC;
    int nel = n - ebase;
    if (nel <= 0) return;
    if (nel > EPC) nel = EPC;

    for (int e0 = 0; e0 < nel; ++e0) {
        const int e = ebase + e0;
        __syncthreads();   // prev P3 ready / smem reuse boundary

        if (wrp == 0) {
            if (e0 > 0) do_final(e - 1);
        } else if (tid >= 64 && tid < 112) {
            const int t = tid - 64;
            const int which = t >> 4, idx = t & 15;
            const int row = (which == 0) ? gI[e] : (which == 1 ? gJ[e] : gK[e]);
            const float* src = (which == 0) ? A : (which == 1 ? Bm : Cm);
            sm[S_ABC + t] = src[row * 16 + idx];
        }
        __syncthreads();

        // BC outer product + WA
        sm[S_BC + tid] = sm[S_ABC + 16 + (tid >> 4)] * sm[S_ABC + 32 + (tid & 15)];
        {
            const float a0 = sm[S_ABC + 2 * wrp], a1v = sm[S_ABC + 2 * wrp + 1];
            ((float4*)(sm + S_WA))[wrp * 32 + lane] = make_float4(
                fmaf(w0r[0], a0, w0r[4] * a1v),
                fmaf(w0r[1], a0, w0r[5] * a1v),
                fmaf(w0r[2], a0, w0r[6] * a1v),
                fmaf(w0r[3], a0, w0r[7] * a1v));
        }
        __syncthreads();

        layer0(0);
        __syncthreads();

        mma1();
        __syncthreads();

        // merged: y1-reduce(half0) + layer0(half1)
        {
            float s0, s1, s2, s3;
            reduce_sum(s0, s1, s2, s3);
            layer0(1);
            reduce_emit(0, s0, s1, s2, s3);
        }
        __syncthreads();

        mma1();
        __syncthreads();

        {
            float s0, s1, s2, s3;
            reduce_sum(s0, s1, s2, s3);
            reduce_emit(1, s0, s1, s2, s3);
        }
        __syncthreads();

        // layer2 mma: warp = K-octant, both m-tiles
        {
            const uint32_t rowb2 = (uint32_t)(((lane & 7) * 132 + wrp * 16 + ((lane >> 3) << 2)) * 4);
            uint32_t bb0,bb1,bb2,bb3;
            ldm4(bb0,bb1,bb2,bb3, smbase + S_B2*4 + rowb2);
#pragma unroll
            for (int mt2 = 0; mt2 < 2; ++mt2) {
                const uint32_t* a = a2 + mt2 * 8;
                float c0 = 0.f, c1 = 0.f, c2 = 0.f, c3 = 0.f;
                mma_f16(c0,c1,c2,c3, a[0],a[1],a[2],a[3], bb0,bb1);
                mma_f16(c0,c1,c2,c3, a[4],a[5],a[6],a[7], bb2,bb3);
                float* p = sm + S_P2 + (2 * wrp + mt2) * P2WS + gid * 8 + (gid >> 2) * 4 + 2 * tig;
                *(float2*)p        = make_float2(c0, c1);
                *(float2*)(p + 72) = make_float2(c2, c3);
            }
        }
        __syncthreads();

        // y2 reduce over 8 octants -> Y2[q2][f]
        if (tid < 64) {
            float s0 = 0.f, s1 = 0.f, s2 = 0.f, s3 = 0.f;
#pragma unroll
            for (int oct = 0; oct < 8; ++oct) {
                const float4 p = *(const float4*)&sm[ybase + (2 * oct + ymt) * P2WS];
                s0 += p.x; s1 += p.y; s2 += p.z; s3 += p.w;
            }
            sm[S_Y2 + (4 * yq2g + 0) * 32 + yc] = fmaxf(s0 + bias2, 0.f);
            sm[S_Y2 + (4 * yq2g + 1) * 32 + yc] = fmaxf(s1 + bias2, 0.f);
            sm[S_Y2 + (4 * yq2g + 2) * 32 + yc] = fmaxf(s2 + bias2, 0.f);
            sm[S_Y2 + (4 * yq2g + 3) * 32 + yc] = fmaxf(s3 + bias2, 0.f);
        }
        __syncthreads();

        // layer3 partial: warp = 4-channel slice, lane = f; W3 packed fp16
        {
            float acc = 0.f;
#pragma unroll
            for (int q2 = 0; q2 < 8; ++q2) {
                const float4 y2v = *(const float4*)&sm[S_Y2 + q2 * 32 + 4 * wrp];
                const uint2 wp = *(const uint2*)&smu[S_W3S + ((q2 * 8 + wrp) * 32 + lane) * 2];
                const float2 f01 = __half22float2(*(const __half2*)&wp.x);
                const float2 f23 = __half22float2(*(const __half2*)&wp.y);
                acc = fmaf(f01.x, y2v.x, acc);
                acc = fmaf(f01.y, y2v.y, acc);
                acc = fmaf(f23.x, y2v.z, acc);
                acc = fmaf(f23.y, y2v.w, acc);
            }
            sm[S_P3 + wrp * 32 + lane] = acc;
        }
        // next iteration's top barrier covers P3
    }

    __syncthreads();
    if (wrp == 0) do_final(ebase + nel - 1);
}

extern "C" void kernel_launch(void* const* d_in, const int* in_sizes, int n_in,
                              void* d_out, int out_size) {
    const int*   gI  = (const int*)d_in[0];
    const int*   gJ  = (const int*)d_in[1];
    const int*   gK  = (const int*)d_in[2];
    const float* A   = (const float*)d_in[3];
    const float* B   = (const float*)d_in[4];
    const float* C   = (const float*)d_in[5];
    const float* W0  = (const float*)d_in[6];
    const float* b0  = (const float*)d_in[7];
    const float* W1  = (const float*)d_in[8];
    const float* b1  = (const float*)d_in[9];
    const float* W2  = (const float*)d_in[10];
    const float* b2  = (const float*)d_in[11];
    const float* W3  = (const float*)d_in[12];
    const float* b3  = (const float*)d_in[13];
    const float* FCW = (const float*)d_in[14];
    const float* FCB = (const float*)d_in[15];

    cudaFuncSetAttribute(ntc_fused, cudaFuncAttributeMaxDynamicSharedMemorySize, SMEM_BYTES);

    const int n = in_sizes[0];
    const int grid = (n + EPC - 1) / EPC;
    ntc_fused<<<grid, 256, SMEM_BYTES>>>(gI, gJ, gK, A, B, C, W0, b0, W1, b1, W2, b2,
                                         W3, b3, FCW, FCB, (float*)d_out, n);
}

// round 16
// speedup vs baseline: 1.6892x; 1.0064x over previous
#include <cuda_runtime.h>
#include <cuda_fp16.h>
#include <cstdint>

#define EPC 8
// word offsets in dynamic smem
#define S_B1  0        // [32 rows][132] fp16x2 (layer1 B, one half at a time)
#define S_ABC 4224     // 48
#define S_BC  4288     // 16x16
#define S_WA  4544     // float4[8][32]
#define S_P1  5568     // 8 rows x 580 (row = 2*kq+mt)
#define P1WS  580
#define S_P2  10208    // 16 rows x 148 (row = 2*oct+mt)
#define P2WS  148
#define S_B2  12576    // [q2 8][132] fp16x2
#define S_Y2  13632    // [q2][f]
#define S_P3  13888
#define S_W3S 14144    // packed fp16: uint2[(q2*8+cq)*32+f]
#define S_W0T 18240    // W0 transposed [t][c] (256)
#define SMW   18496
#define SMEM_BYTES (SMW * 4)

__device__ __forceinline__ uint32_t pack_f16x2(float lo, float hi) {
    uint32_t d;
    asm("cvt.rn.f16x2.f32 %0, %1, %2;" : "=r"(d) : "f"(hi), "f"(lo));
    return d;
}
__device__ __forceinline__ void mma_f16(float& c0, float& c1, float& c2, float& c3,
                                        uint32_t a0, uint32_t a1, uint32_t a2, uint32_t a3,
                                        uint32_t b0, uint32_t b1) {
    asm("mma.sync.aligned.m16n8k16.row.col.f32.f16.f16.f32 "
        "{%0,%1,%2,%3},{%4,%5,%6,%7},{%8,%9},{%0,%1,%2,%3};"
        : "+f"(c0), "+f"(c1), "+f"(c2), "+f"(c3)
        : "r"(a0), "r"(a1), "r"(a2), "r"(a3), "r"(b0), "r"(b1));
}
__device__ __forceinline__ void ldm4(uint32_t& r0, uint32_t& r1, uint32_t& r2, uint32_t& r3,
                                     uint32_t saddr) {
    asm volatile("ldmatrix.sync.aligned.m8n8.x4.shared.b16 {%0,%1,%2,%3}, [%4];"
                 : "=r"(r0), "=r"(r1), "=r"(r2), "=r"(r3) : "r"(saddr));
}

__global__ __launch_bounds__(256, 3)
void ntc_fused(const int* __restrict__ gI, const int* __restrict__ gJ, const int* __restrict__ gK,
               const float* __restrict__ A, const float* __restrict__ Bm, const float* __restrict__ Cm,
               const float* __restrict__ W0, const float* __restrict__ b0,
               const float* __restrict__ W1, const float* __restrict__ b1,
               const float* __restrict__ W2, const float* __restrict__ b2,
               const float* __restrict__ W3, const float* __restrict__ b3,
               const float* __restrict__ FCW, const float* __restrict__ FCB,
               float* __restrict__ out, int n)
{
    extern __shared__ float sm[];
    uint32_t* smu = (uint32_t*)sm;
    const uint32_t smbase = (uint32_t)__cvta_generic_to_shared(sm);

    const int tid  = threadIdx.x;
    const int lane = tid & 31;
    const int wrp  = tid >> 5;
    const int tig  = lane & 3;
    const int gid  = lane >> 2;
    const int ntg  = wrp & 1;     // layer1: nt-group
    const int kq   = wrp >> 1;    // layer1: K-quarter

    // ---- A fragments, single-term fp16, BOTH m-tiles per warp ----
    uint32_t a1[32];   // layer1: [mt][ch*4+r]
#pragma unroll
    for (int mt2 = 0; mt2 < 2; ++mt2)
#pragma unroll
        for (int ch = 0; ch < 4; ++ch)
#pragma unroll
            for (int r = 0; r < 4; ++r) {
                const int fr = mt2 * 16 + gid + (r & 1) * 8;
                const int k  = kq * 64 + ch * 16 + (r >> 1) * 8 + 2 * tig;
                const float2 w = *(const float2*)&W1[fr * 256 + k];
                a1[mt2 * 16 + ch * 4 + r] = pack_f16x2(w.x, w.y);
            }
    uint32_t a2[16];   // layer2: [mt][kc*4+r], K-octant = wrp
#pragma unroll
    for (int mt2 = 0; mt2 < 2; ++mt2)
#pragma unroll
        for (int kc = 0; kc < 2; ++kc)
#pragma unroll
            for (int r = 0; r < 4; ++r) {
                const int fr = mt2 * 16 + gid + (r & 1) * 8;
                const int k  = wrp * 32 + kc * 16 + (r >> 1) * 8 + 2 * tig;
                const float2 w = *(const float2*)&W2[fr * 256 + k];
                a2[mt2 * 8 + kc * 4 + r] = pack_f16x2(w.x, w.y);
            }

    // ---- W3 packed fp16 quads ----
#pragma unroll
    for (int r = 0; r < 16; ++r) {
        const int idx = tid + 256 * r;    // pair index: f | cp | q2
        const int f = idx >> 7, rem = idx & 127, cp = rem >> 3, q2 = rem & 7;
        const float w3a = W3[f * 256 + (2 * cp) * 8 + q2];
        const float w3b = W3[f * 256 + (2 * cp + 1) * 8 + q2];
        smu[S_W3S + ((q2 * 8 + (cp >> 1)) * 32 + f) * 2 + (cp & 1)] = pack_f16x2(w3a, w3b);
    }
    // ---- W0 transposed [t][c] into smem (replaces w0r registers) ----
    sm[S_W0T + (tid & 7) * 32 + (tid >> 3)] = W0[tid];

    const float bias0 = b0[lane], bias1 = b1[lane], bias2 = b2[lane], bias3 = b3[lane];
    const float fcw = FCW[lane], fcb = FCB[0];

    const int wd = (wrp >> 2) & 1, wh = (wrp >> 1) & 1, ww = wrp & 1;
    // y1-reduce mapping
    const int rf   = tid & 31;
    const int rt1g = (tid >> 5) & 1;
    const int rq2i = tid >> 6;
    const int rmt = rf >> 4, r16 = rf & 15;
    const int rbase = S_P1 + rq2i * 144 + r16 * 8 + (r16 >> 2) * 4 + rt1g * 4;
    // y2-reduce mapping (tid<64)
    const int yc = tid & 31, yq2g = (tid >> 5) & 1;
    const int ymt = yc >> 4, yr16 = yc & 15;
    const int ybase = S_P2 + yr16 * 8 + (yr16 >> 2) * 4 + yq2g * 4;

    auto do_final = [&](int eo) {
        float s3 = sm[S_P3 + lane];
#pragma unroll
        for (int wi = 1; wi < 8; ++wi) s3 += sm[S_P3 + wi * 32 + lane];
        const float y3 = fmaxf(s3 + bias3, 0.f);
        float vv = fcw * y3;
#pragma unroll
        for (int off = 16; off; off >>= 1)
            vv += __shfl_xor_sync(0xffffffffu, vv, off);
        if (lane == 0)
            out[eo] = 1.0f / (1.0f + __expf(-(vv + fcb)));
    };

    // ---- layer0 for one d2-half: B1 rows as fp16x2 ----
    auto layer0 = [&](int half) {
        const int D1 = 2 * half + wd;
        const float4 wa0 = ((const float4*)(sm + S_WA))[(2 * D1) * 32 + lane];
        const float4 wa1 = ((const float4*)(sm + S_WA))[(2 * D1 + 1) * 32 + lane];
#pragma unroll
        for (int q2i = 0; q2i < 4; ++q2i) {
            const int H1 = 2 * (q2i >> 1) + wh, Wd1 = 2 * (q2i & 1) + ww;
            float v[8];
#pragma unroll
            for (int qh = 0; qh < 2; ++qh) {
                const float4 bcA = *(const float4*)&sm[S_BC + (4 * H1 + 2 * qh) * 16 + 4 * Wd1];
                const float4 bcB = *(const float4*)&sm[S_BC + (4 * H1 + 2 * qh + 1) * 16 + 4 * Wd1];
                v[qh*2+0]   = fmaxf(fmaf(wa0.x, bcA.x, fmaf(wa0.y, bcA.y, fmaf(wa0.z, bcB.x, fmaf(wa0.w, bcB.y, bias0)))), 0.f);
                v[qh*2+1]   = fmaxf(fmaf(wa0.x, bcA.z, fmaf(wa0.y, bcA.w, fmaf(wa0.z, bcB.z, fmaf(wa0.w, bcB.w, bias0)))), 0.f);
                v[4+qh*2+0] = fmaxf(fmaf(wa1.x, bcA.x, fmaf(wa1.y, bcA.y, fmaf(wa1.z, bcB.x, fmaf(wa1.w, bcB.y, bias0)))), 0.f);
                v[4+qh*2+1] = fmaxf(fmaf(wa1.x, bcA.z, fmaf(wa1.y, bcA.w, fmaf(wa1.z, bcB.z, fmaf(wa1.w, bcB.w, bias0)))), 0.f);
            }
            const int rowoff = (q2i * 8 + wrp) * 132 + 4 * lane;
            *(uint4*)&smu[S_B1 + rowoff] = make_uint4(
                pack_f16x2(v[0], v[1]), pack_f16x2(v[2], v[3]),
                pack_f16x2(v[4], v[5]), pack_f16x2(v[6], v[7]));
        }
    };

    // ---- layer1 mma: warp = (kq, ntg), both m-tiles ----
    auto mma1 = [&]() {
#pragma unroll
        for (int nti = 0; nti < 2; ++nti) {
            const int nt = 2 * ntg + nti;
            const uint32_t rowb = (uint32_t)(((nt * 8 + (lane & 7)) * 132 + kq * 32 + ((lane >> 3) << 2)) * 4);
            uint32_t bb0,bb1,bb2,bb3,bb4,bb5,bb6,bb7;
            ldm4(bb0,bb1,bb2,bb3, smbase + S_B1*4 + rowb);
            ldm4(bb4,bb5,bb6,bb7, smbase + S_B1*4 + rowb + 64);
#pragma unroll
            for (int mt2 = 0; mt2 < 2; ++mt2) {
                const uint32_t* a = a1 + mt2 * 16;
                float c0 = 0.f, c1 = 0.f, c2 = 0.f, c3 = 0.f;
                mma_f16(c0,c1,c2,c3, a[0],a[1],a[2],a[3],     bb0,bb1);
                mma_f16(c0,c1,c2,c3, a[4],a[5],a[6],a[7],     bb2,bb3);
                mma_f16(c0,c1,c2,c3, a[8],a[9],a[10],a[11],   bb4,bb5);
                mma_f16(c0,c1,c2,c3, a[12],a[13],a[14],a[15], bb6,bb7);
                float* p = sm + S_P1 + (2 * kq + mt2) * P1WS + nt * 144 + gid * 8 + (gid >> 2) * 4 + 2 * tig;
                *(float2*)p        = make_float2(c0, c1);
                *(float2*)(p + 72) = make_float2(c2, c3);
            }
        }
    };

    auto reduce_sum = [&](float& s0, float& s1, float& s2, float& s3) {
        s0 = s1 = s2 = s3 = 0.f;
#pragma unroll
        for (int kqi = 0; kqi < 4; ++kqi) {
            const float4 p = *(const float4*)&sm[rbase + (rmt + 2 * kqi) * P1WS];
            s0 += p.x; s1 += p.y; s2 += p.z; s3 += p.w;
        }
    };
    auto reduce_emit = [&](int half, float s0, float s1, float s2, float s3) {
        const float y0  = fmaxf(s0 + bias1, 0.f);
        const float y1v = fmaxf(s1 + bias1, 0.f);
        const float y2v = fmaxf(s2 + bias1, 0.f);
        const float y3v = fmaxf(s3 + bias1, 0.f);
        const int q2 = half * 4 + rq2i;
        const int kp = rf * 4 + rt1g * 2;
        *(uint2*)&smu[S_B2 + q2 * 132 + kp] =
            make_uint2(pack_f16x2(y0, y1v), pack_f16x2(y2v, y3v));
    };

    const int ebase = blockIdx.x * EPC;
    int nel = n - ebase;
    if (nel <= 0) return;
    if (nel > EPC) nel = EPC;

    for (int e0 = 0; e0 < nel; ++e0) {
        const int e = ebase + e0;
        __syncthreads();   // prev P3 ready / smem reuse boundary (also covers prologue)

        if (wrp == 0) {
            if (e0 > 0) do_final(e - 1);
        } else if (tid >= 64 && tid < 112) {
            const int t = tid - 64;
            const int which = t >> 4, idx = t & 15;
            const int row = (which == 0) ? gI[e] : (which == 1 ? gJ[e] : gK[e]);
            const float* src = (which == 0) ? A : (which == 1 ? Bm : Cm);
            sm[S_ABC + t] = src[row * 16 + idx];
        }
        __syncthreads();

        // BC outer product + WA (W0 from smem, transposed: conflict-free)
        sm[S_BC + tid] = sm[S_ABC + 16 + (tid >> 4)] * sm[S_ABC + 32 + (tid & 15)];
        {
            const float a0 = sm[S_ABC + 2 * wrp], a1v = sm[S_ABC + 2 * wrp + 1];
            float w0v[8];
#pragma unroll
            for (int t = 0; t < 8; ++t) w0v[t] = sm[S_W0T + t * 32 + lane];
            ((float4*)(sm + S_WA))[wrp * 32 + lane] = make_float4(
                fmaf(w0v[0], a0, w0v[4] * a1v),
                fmaf(w0v[1], a0, w0v[5] * a1v),
                fmaf(w0v[2], a0, w0v[6] * a1v),
                fmaf(w0v[3], a0, w0v[7] * a1v));
        }
        __syncthreads();

        layer0(0);
        __syncthreads();

        mma1();
        __syncthreads();

        // merged: y1-reduce(half0) + layer0(half1)
        {
            float s0, s1, s2, s3;
            reduce_sum(s0, s1, s2, s3);
            layer0(1);
            reduce_emit(0, s0, s1, s2, s3);
        }
        __syncthreads();

        mma1();
        __syncthreads();

        {
            float s0, s1, s2, s3;
            reduce_sum(s0, s1, s2, s3);
            reduce_emit(1, s0, s1, s2, s3);
        }
        __syncthreads();

        // layer2 mma: warp = K-octant, both m-tiles
        {
            const uint32_t rowb2 = (uint32_t)(((lane & 7) * 132 + wrp * 16 + ((lane >> 3) << 2)) * 4);
            uint32_t bb0,bb1,bb2,bb3;
            ldm4(bb0,bb1,bb2,bb3, smbase + S_B2*4 + rowb2);
#pragma unroll
            for (int mt2 = 0; mt2 < 2; ++mt2) {
                const uint32_t* a = a2 + mt2 * 8;
                float c0 = 0.f, c1 = 0.f, c2 = 0.f, c3 = 0.f;
                mma_f16(c0,c1,c2,c3, a[0],a[1],a[2],a[3], bb0,bb1);
                mma_f16(c0,c1,c2,c3, a[4],a[5],a[6],a[7], bb2,bb3);
                float* p = sm + S_P2 + (2 * wrp + mt2) * P2WS + gid * 8 + (gid >> 2) * 4 + 2 * tig;
                *(float2*)p        = make_float2(c0, c1);
                *(float2*)(p + 72) = make_float2(c2, c3);
            }
        }
        __syncthreads();

        // y2 reduce over 8 octants -> Y2[q2][f]
        if (tid < 64) {
            float s0 = 0.f, s1 = 0.f, s2 = 0.f, s3 = 0.f;
#pragma unroll
            for (int oct = 0; oct < 8; ++oct) {
                const float4 p = *(const float4*)&sm[ybase + (2 * oct + ymt) * P2WS];
                s0 += p.x; s1 += p.y; s2 += p.z; s3 += p.w;
            }
            sm[S_Y2 + (4 * yq2g + 0) * 32 + yc] = fmaxf(s0 + bias2, 0.f);
            sm[S_Y2 + (4 * yq2g + 1) * 32 + yc] = fmaxf(s1 + bias2, 0.f);
            sm[S_Y2 + (4 * yq2g + 2) * 32 + yc] = fmaxf(s2 + bias2, 0.f);
            sm[S_Y2 + (4 * yq2g + 3) * 32 + yc] = fmaxf(s3 + bias2, 0.f);
        }
        __syncthreads();

        // layer3 partial: warp = 4-channel slice, lane = f; W3 packed fp16
        {
            float acc = 0.f;
#pragma unroll
            for (int q2 = 0; q2 < 8; ++q2) {
                const float4 y2v = *(const float4*)&sm[S_Y2 + q2 * 32 + 4 * wrp];
                const uint2 wp = *(const uint2*)&smu[S_W3S + ((q2 * 8 + wrp) * 32 + lane) * 2];
                const float2 f01 = __half22float2(*(const __half2*)&wp.x);
                const float2 f23 = __half22float2(*(const __half2*)&wp.y);
                acc = fmaf(f01.x, y2v.x, acc);
                acc = fmaf(f01.y, y2v.y, acc);
                acc = fmaf(f23.x, y2v.z, acc);
                acc = fmaf(f23.y, y2v.w, acc);
            }
            sm[S_P3 + wrp * 32 + lane] = acc;
        }
        // next iteration's top barrier covers P3
    }

    __syncthreads();
    if (wrp == 0) do_final(ebase + nel - 1);
}

extern "C" void kernel_launch(void* const* d_in, const int* in_sizes, int n_in,
                              void* d_out, int out_size) {
    const int*   gI  = (const int*)d_in[0];
    const int*   gJ  = (const int*)d_in[1];
    const int*   gK  = (const int*)d_in[2];
    const float* A   = (const float*)d_in[3];
    const float* B   = (const float*)d_in[4];
    const float* C   = (const float*)d_in[5];
    const float* W0  = (const float*)d_in[6];
    const float* b0  = (const float*)d_in[7];
    const float* W1  = (const float*)d_in[8];
    const float* b1  = (const float*)d_in[9];
    const float* W2  = (const float*)d_in[10];
    const float* b2  = (const float*)d_in[11];
    const float* W3  = (const float*)d_in[12];
    const float* b3  = (const float*)d_in[13];
    const float* FCW = (const float*)d_in[14];
    const float* FCB = (const float*)d_in[15];

    cudaFuncSetAttribute(ntc_fused, cudaFuncAttributeMaxDynamicSharedMemorySize, SMEM_BYTES);

    const int n = in_sizes[0];
    const int grid = (n + EPC - 1) / EPC;
    ntc_fused<<<grid, 256, SMEM_BYTES>>>(gI, gJ, gK, A, B, C, W0, b0, W1, b1, W2, b2,
                                         W3, b3, FCW, FCB, (float*)d_out, n);
}

// round 17
// speedup vs baseline: 1.7183x; 1.0172x over previous
#include <cuda_runtime.h>
#include <cuda_fp16.h>
#include <cstdint>

#define EPC 8
// word offsets in dynamic smem
#define S_B1A 0        // [32 rows][132] fp16x2, half 0
#define S_B1B 4224     // half 1
#define S_ABC 8448     // 48
#define S_BC  8512     // 16x16
#define S_WA  8768     // float4[8][32]
#define S_P2  9792     // 16 rows x 148 (row = 2*oct+mt)
#define P2WS  148
#define S_B2  12160    // [q2 8][132] fp16x2
#define S_Y2  13216    // [q2][f]
#define S_P3  13472
#define S_W3S 13728    // packed fp16: uint2[(q2*8+cq)*32+f] (4096 words)
#define S_W0T 17824    // W0 transposed [t][c] (256)
#define SMW   18080
#define SMEM_BYTES (SMW * 4)

__device__ __forceinline__ uint32_t pack_f16x2(float lo, float hi) {
    uint32_t d;
    asm("cvt.rn.f16x2.f32 %0, %1, %2;" : "=r"(d) : "f"(hi), "f"(lo));
    return d;
}
__device__ __forceinline__ void mma_f16(float& c0, float& c1, float& c2, float& c3,
                                        uint32_t a0, uint32_t a1, uint32_t a2, uint32_t a3,
                                        uint32_t b0, uint32_t b1) {
    asm("mma.sync.aligned.m16n8k16.row.col.f32.f16.f16.f32 "
        "{%0,%1,%2,%3},{%4,%5,%6,%7},{%8,%9},{%0,%1,%2,%3};"
        : "+f"(c0), "+f"(c1), "+f"(c2), "+f"(c3)
        : "r"(a0), "r"(a1), "r"(a2), "r"(a3), "r"(b0), "r"(b1));
}
__device__ __forceinline__ void ldm4(uint32_t& r0, uint32_t& r1, uint32_t& r2, uint32_t& r3,
                                     uint32_t saddr) {
    asm volatile("ldmatrix.sync.aligned.m8n8.x4.shared.b16 {%0,%1,%2,%3}, [%4];"
                 : "=r"(r0), "=r"(r1), "=r"(r2), "=r"(r3) : "r"(saddr));
}

__global__ __launch_bounds__(256, 2)
void ntc_fused(const int* __restrict__ gI, const int* __restrict__ gJ, const int* __restrict__ gK,
               const float* __restrict__ A, const float* __restrict__ Bm, const float* __restrict__ Cm,
               const float* __restrict__ W0, const float* __restrict__ b0,
               const float* __restrict__ W1, const float* __restrict__ b1,
               const float* __restrict__ W2, const float* __restrict__ b2,
               const float* __restrict__ W3, const float* __restrict__ b3,
               const float* __restrict__ FCW, const float* __restrict__ FCB,
               float* __restrict__ out, int n)
{
    extern __shared__ float sm[];
    uint32_t* smu = (uint32_t*)sm;
    const uint32_t smbase = (uint32_t)__cvta_generic_to_shared(sm);

    const int tid  = threadIdx.x;
    const int lane = tid & 31;
    const int wrp  = tid >> 5;
    const int tig  = lane & 3;
    const int gid  = lane >> 2;
    const int nt1  = wrp & 3;     // layer1: q2-cell within half
    const int mt1  = wrp >> 2;    // layer1: m-tile

    // ---- layer1 A fragments: FULL K=256, one m-tile (fp16 single-term) ----
    uint32_t a1[64];   // [s=0..15][r=0..3]
#pragma unroll
    for (int s = 0; s < 16; ++s)
#pragma unroll
        for (int r = 0; r < 4; ++r) {
            const int fr = mt1 * 16 + gid + (r & 1) * 8;
            const int k  = s * 16 + (r >> 1) * 8 + 2 * tig;
            const float2 w = *(const float2*)&W1[fr * 256 + k];
            a1[s * 4 + r] = pack_f16x2(w.x, w.y);
        }
    // ---- layer2 A fragments: K-octant = wrp, both m-tiles ----
    uint32_t a2[16];
#pragma unroll
    for (int mt2 = 0; mt2 < 2; ++mt2)
#pragma unroll
        for (int kc = 0; kc < 2; ++kc)
#pragma unroll
            for (int r = 0; r < 4; ++r) {
                const int fr = mt2 * 16 + gid + (r & 1) * 8;
                const int k  = wrp * 32 + kc * 16 + (r >> 1) * 8 + 2 * tig;
                const float2 w = *(const float2*)&W2[fr * 256 + k];
                a2[mt2 * 8 + kc * 4 + r] = pack_f16x2(w.x, w.y);
            }

    // ---- W3 packed fp16 quads ----
#pragma unroll
    for (int r = 0; r < 16; ++r) {
        const int idx = tid + 256 * r;    // pair index: f | cp | q2
        const int f = idx >> 7, rem = idx & 127, cp = rem >> 3, q2 = rem & 7;
        const float w3a = W3[f * 256 + (2 * cp) * 8 + q2];
        const float w3b = W3[f * 256 + (2 * cp + 1) * 8 + q2];
        smu[S_W3S + ((q2 * 8 + (cp >> 1)) * 32 + f) * 2 + (cp & 1)] = pack_f16x2(w3a, w3b);
    }
    // ---- W0 transposed [t][c] into smem ----
    sm[S_W0T + (tid & 7) * 32 + (tid >> 3)] = W0[tid];

    const float bias0 = b0[lane], bias2 = b2[lane], bias3 = b3[lane];
    const float b1a = b1[mt1 * 16 + gid];      // layer1 bias for f = mt1*16+gid
    const float b1b = b1[mt1 * 16 + gid + 8];  // and f+8
    const float fcw = FCW[lane], fcb = FCB[0];

    const int wd = (wrp >> 2) & 1, wh = (wrp >> 1) & 1, ww = wrp & 1;
    // y2-reduce mapping (tid<64); P2 rows = 2*oct + mt
    const int yc = tid & 31, yq2g = (tid >> 5) & 1;
    const int ymt = yc >> 4, yr16 = yc & 15;
    const int ybase = S_P2 + yr16 * 8 + (yr16 >> 2) * 4 + yq2g * 4;

    auto do_final = [&](int eo) {
        float s3 = sm[S_P3 + lane];
#pragma unroll
        for (int wi = 1; wi < 8; ++wi) s3 += sm[S_P3 + wi * 32 + lane];
        const float y3 = fmaxf(s3 + bias3, 0.f);
        float vv = fcw * y3;
#pragma unroll
        for (int off = 16; off; off >>= 1)
            vv += __shfl_xor_sync(0xffffffffu, vv, off);
        if (lane == 0)
            out[eo] = 1.0f / (1.0f + __expf(-(vv + fcb)));
    };

    // ---- layer0 for one d2-half -> B1 buffer ----
    auto layer0 = [&](int half, int b1base) {
        const int D1 = 2 * half + wd;
        const float4 wa0 = ((const float4*)(sm + S_WA))[(2 * D1) * 32 + lane];
        const float4 wa1 = ((const float4*)(sm + S_WA))[(2 * D1 + 1) * 32 + lane];
#pragma unroll
        for (int q2i = 0; q2i < 4; ++q2i) {
            const int H1 = 2 * (q2i >> 1) + wh, Wd1 = 2 * (q2i & 1) + ww;
            float v[8];
#pragma unroll
            for (int qh = 0; qh < 2; ++qh) {
                const float4 bcA = *(const float4*)&sm[S_BC + (4 * H1 + 2 * qh) * 16 + 4 * Wd1];
                const float4 bcB = *(const float4*)&sm[S_BC + (4 * H1 + 2 * qh + 1) * 16 + 4 * Wd1];
                v[qh*2+0]   = fmaxf(fmaf(wa0.x, bcA.x, fmaf(wa0.y, bcA.y, fmaf(wa0.z, bcB.x, fmaf(wa0.w, bcB.y, bias0)))), 0.f);
                v[qh*2+1]   = fmaxf(fmaf(wa0.x, bcA.z, fmaf(wa0.y, bcA.w, fmaf(wa0.z, bcB.z, fmaf(wa0.w, bcB.w, bias0)))), 0.f);
                v[4+qh*2+0] = fmaxf(fmaf(wa1.x, bcA.x, fmaf(wa1.y, bcA.y, fmaf(wa1.z, bcB.x, fmaf(wa1.w, bcB.y, bias0)))), 0.f);
                v[4+qh*2+1] = fmaxf(fmaf(wa1.x, bcA.z, fmaf(wa1.y, bcA.w, fmaf(wa1.z, bcB.z, fmaf(wa1.w, bcB.w, bias0)))), 0.f);
            }
            const int rowoff = (q2i * 8 + wrp) * 132 + 4 * lane;
            *(uint4*)&smu[b1base + rowoff] = make_uint4(
                pack_f16x2(v[0], v[1]), pack_f16x2(v[2], v[3]),
                pack_f16x2(v[4], v[5]), pack_f16x2(v[6], v[7]));
        }
    };

    // ---- layer1 mma: warp = (nt1, mt1), full K=256; emits y1 directly into B2 ----
    auto mma1 = [&](int half, int b1base) {
        float c0 = 0.f, c1 = 0.f, c2 = 0.f, c3 = 0.f;   // even-kc accumulators
        float d0 = 0.f, d1 = 0.f, d2 = 0.f, d3 = 0.f;   // odd-step accumulators
#pragma unroll
        for (int kc = 0; kc < 4; ++kc) {
            const uint32_t rowb = (uint32_t)(((nt1 * 8 + (lane & 7)) * 132 + kc * 32 + ((lane >> 3) << 2)) * 4);
            uint32_t bb0,bb1,bb2,bb3,bb4,bb5,bb6,bb7;
            ldm4(bb0,bb1,bb2,bb3, smbase + b1base*4 + rowb);
            ldm4(bb4,bb5,bb6,bb7, smbase + b1base*4 + rowb + 64);
            const uint32_t* a = a1 + kc * 16;
            mma_f16(c0,c1,c2,c3, a[0],a[1],a[2],a[3],     bb0,bb1);
            mma_f16(d0,d1,d2,d3, a[4],a[5],a[6],a[7],     bb2,bb3);
            mma_f16(c0,c1,c2,c3, a[8],a[9],a[10],a[11],   bb4,bb5);
            mma_f16(d0,d1,d2,d3, a[12],a[13],a[14],a[15], bb6,bb7);
        }
        const float y0 = fmaxf(c0 + d0 + b1a, 0.f);
        const float y1 = fmaxf(c1 + d1 + b1a, 0.f);
        const float y2 = fmaxf(c2 + d2 + b1b, 0.f);
        const float y3 = fmaxf(c3 + d3 + b1b, 0.f);
        const int q2 = half * 4 + nt1;
        smu[S_B2 + q2 * 132 + mt1 * 64 + lane]      = pack_f16x2(y0, y1);
        smu[S_B2 + q2 * 132 + mt1 * 64 + 32 + lane] = pack_f16x2(y2, y3);
    };

    const int ebase = blockIdx.x * EPC;
    int nel = n - ebase;
    if (nel <= 0) return;
    if (nel > EPC) nel = EPC;

    for (int e0 = 0; e0 < nel; ++e0) {
        const int e = ebase + e0;
        __syncthreads();   // prev P3 ready / smem reuse boundary (also covers prologue)

        if (wrp == 0) {
            if (e0 > 0) do_final(e - 1);
        } else if (tid >= 64 && tid < 112) {
            const int t = tid - 64;
            const int which = t >> 4, idx = t & 15;
            const int row = (which == 0) ? gI[e] : (which == 1 ? gJ[e] : gK[e]);
            const float* src = (which == 0) ? A : (which == 1 ? Bm : Cm);
            sm[S_ABC + t] = src[row * 16 + idx];
        }
        __syncthreads();

        // BC outer product + WA (W0 from smem)
        sm[S_BC + tid] = sm[S_ABC + 16 + (tid >> 4)] * sm[S_ABC + 32 + (tid & 15)];
        {
            const float a0 = sm[S_ABC + 2 * wrp], a1v = sm[S_ABC + 2 * wrp + 1];
            float w0v[8];
#pragma unroll
            for (int t = 0; t < 8; ++t) w0v[t] = sm[S_W0T + t * 32 + lane];
            ((float4*)(sm + S_WA))[wrp * 32 + lane] = make_float4(
                fmaf(w0v[0], a0, w0v[4] * a1v),
                fmaf(w0v[1], a0, w0v[5] * a1v),
                fmaf(w0v[2], a0, w0v[6] * a1v),
                fmaf(w0v[3], a0, w0v[7] * a1v));
        }
        __syncthreads();

        layer0(0, S_B1A);
        __syncthreads();

        // overlapped: layer0(half1)->B1B + mma1(half0 from B1A)->B2 rows 0..3
        layer0(1, S_B1B);
        mma1(0, S_B1A);
        __syncthreads();

        mma1(1, S_B1B);
        __syncthreads();

        // layer2 mma: warp = K-octant, both m-tiles
        {
            const uint32_t rowb2 = (uint32_t)(((lane & 7) * 132 + wrp * 16 + ((lane >> 3) << 2)) * 4);
            uint32_t bb0,bb1,bb2,bb3;
            ldm4(bb0,bb1,bb2,bb3, smbase + S_B2*4 + rowb2);
#pragma unroll
            for (int mt2 = 0; mt2 < 2; ++mt2) {
                const uint32_t* a = a2 + mt2 * 8;
                float c0 = 0.f, c1 = 0.f, c2 = 0.f, c3 = 0.f;
                mma_f16(c0,c1,c2,c3, a[0],a[1],a[2],a[3], bb0,bb1);
                mma_f16(c0,c1,c2,c3, a[4],a[5],a[6],a[7], bb2,bb3);
                float* p = sm + S_P2 + (2 * wrp + mt2) * P2WS + gid * 8 + (gid >> 2) * 4 + 2 * tig;
                *(float2*)p        = make_float2(c0, c1);
                *(float2*)(p + 72) = make_float2(c2, c3);
            }
        }
        __syncthreads();

        // y2 reduce over 8 octants -> Y2[q2][f]
        if (tid < 64) {
            float s0 = 0.f, s1 = 0.f, s2 = 0.f, s3 = 0.f;
#pragma unroll
            for (int oct = 0; oct < 8; ++oct) {
                const float4 p = *(const float4*)&sm[ybase + (2 * oct + ymt) * P2WS];
                s0 += p.x; s1 += p.y; s2 += p.z; s3 += p.w;
            }
            sm[S_Y2 + (4 * yq2g + 0) * 32 + yc] = fmaxf(s0 + bias2, 0.f);
            sm[S_Y2 + (4 * yq2g + 1) * 32 + yc] = fmaxf(s1 + bias2, 0.f);
            sm[S_Y2 + (4 * yq2g + 2) * 32 + yc] = fmaxf(s2 + bias2, 0.f);
            sm[S_Y2 + (4 * yq2g + 3) * 32 + yc] = fmaxf(s3 + bias2, 0.f);
        }
        __syncthreads();

        // layer3 partial: warp = 4-channel slice, lane = f; W3 packed fp16
        {
            float acc = 0.f;
#pragma unroll
            for (int q2 = 0; q2 < 8; ++q2) {
                const float4 y2v = *(const float4*)&sm[S_Y2 + q2 * 32 + 4 * wrp];
                const uint2 wp = *(const uint2*)&smu[S_W3S + ((q2 * 8 + wrp) * 32 + lane) * 2];
                const float2 f01 = __half22float2(*(const __half2*)&wp.x);
                const float2 f23 = __half22float2(*(const __half2*)&wp.y);
                acc = fmaf(f01.x, y2v.x, acc);
                acc = fmaf(f01.y, y2v.y, acc);
                acc = fmaf(f23.x, y2v.z, acc);
                acc = fmaf(f23.y, y2v.w, acc);
            }
            sm[S_P3 + wrp * 32 + lane] = acc;
        }
        // next iteration's top barrier covers P3
    }

    __syncthreads();
    if (wrp == 0) do_final(ebase + nel - 1);
}

extern "C" void kernel_launch(void* const* d_in, const int* in_sizes, int n_in,
                              void* d_out, int out_size) {
    const int*   gI  = (const int*)d_in[0];
    const int*   gJ  = (const int*)d_in[1];
    const int*   gK  = (const int*)d_in[2];
    const float* A   = (const float*)d_in[3];
    const float* B   = (const float*)d_in[4];
    const float* C   = (const float*)d_in[5];
    const float* W0  = (const float*)d_in[6];
    const float* b0  = (const float*)d_in[7];
    const float* W1  = (const float*)d_in[8];
    const float* b1  = (const float*)d_in[9];
    const float* W2  = (const float*)d_in[10];
    const float* b2  = (const float*)d_in[11];
    const float* W3  = (const float*)d_in[12];
    const float* b3  = (const float*)d_in[13];
    const float* FCW = (const float*)d_in[14];
    const float* FCB = (const float*)d_in[15];

    cudaFuncSetAttribute(ntc_fused, cudaFuncAttributeMaxDynamicSharedMemorySize, SMEM_BYTES);

    const int n = in_sizes[0];
    const int grid = (n + EPC - 1) / EPC;
    ntc_fused<<<grid, 256, SMEM_BYTES>>>(gI, gJ, gK, A, B, C, W0, b0, W1, b1, W2, b2,
                                         W3, b3, FCW, FCB, (float*)d_out, n);
}